// round 14
// baseline (speedup 1.0000x reference)
#include <cuda_runtime.h>
#include <cuda_fp16.h>
#include <math.h>
#include <cstdint>

#define NN 100000
#define EG 400000
#define NFEAT 128
#define HID 256
#define NOUTF 128
#define ETOT (EG + NN)
#define SCB ((NN + 255) / 256)

// ---------------- scratch (device globals; no allocation allowed) ----------------
__device__ float g_h[(size_t)NN * HID];            // transformed features h (fp32)
__device__ __half g_xa[(size_t)NN * NFEAT];        // input features, fp16
__device__ __half g_fa[(size_t)NN * HID];          // layer activations, fp16
__device__ __half g_w0t_hi[HID * NFEAT], g_w0t_lo[HID * NFEAT];   // [N][K] fp16 split
__device__ __half g_w1t_hi[HID * HID],   g_w1t_lo[HID * HID];
__device__ __half g_w2t_hi[NOUTF * HID], g_w2t_lo[NOUTF * HID];
__device__ float g_als[NN * 4];
__device__ float g_ald[NN * 4];
__device__ int   g_rowptr[NN + 1];
__device__ int   g_wp[NN + 1];
__device__ int   g_bsum[SCB + 1];
__device__ int   g_col[ETOT];
__device__ int   g_is64;

// ---------------- warp-MMA helpers (portable PTX, sm_80+) ----------------
__device__ __forceinline__ uint32_t smem_u32(const void* p) {
    uint32_t a;
    asm("{ .reg .u64 t; cvta.to.shared.u64 t, %1; cvt.u32.u64 %0, t; }" : "=r"(a) : "l"(p));
    return a;
}
__device__ __forceinline__ void ldmx4(uint32_t* r, uint32_t addr) {
    asm volatile("ldmatrix.sync.aligned.m8n8.x4.shared.b16 {%0,%1,%2,%3}, [%4];"
                 : "=r"(r[0]), "=r"(r[1]), "=r"(r[2]), "=r"(r[3]) : "r"(addr));
}
__device__ __forceinline__ void mma16816h(float* c, const uint32_t* a, const uint32_t* b) {
    asm volatile("mma.sync.aligned.m16n8k16.row.col.f32.f16.f16.f32 "
                 "{%0,%1,%2,%3}, {%4,%5,%6,%7}, {%8,%9}, {%0,%1,%2,%3};"
                 : "+f"(c[0]), "+f"(c[1]), "+f"(c[2]), "+f"(c[3])
                 : "r"(a[0]), "r"(a[1]), "r"(a[2]), "r"(a[3]), "r"(b[0]), "r"(b[1]));
}
__device__ __forceinline__ void cpasync16(uint32_t saddr, const void* gptr, uint32_t srcsz) {
    asm volatile("cp.async.cg.shared.global [%0], [%1], 16, %2;"
                 :: "r"(saddr), "l"(gptr), "r"(srcsz) : "memory");
}
#define CP_COMMIT() asm volatile("cp.async.commit_group;" ::: "memory")
#define CP_WAIT(n)  asm volatile("cp.async.wait_group %0;" :: "n"(n) : "memory")

// ---------------- edge dtype sniffer ----------------
__global__ void detect_k(const int* __restrict__ ew) {
    int all_zero = 1;
    for (int i = 0; i < 64; i++)
        if (ew[2 * i + 1] != 0) { all_zero = 0; break; }
    g_is64 = all_zero;
}
__device__ __forceinline__ int edge_at(const int* ew, long long idx) {
    return g_is64 ? ew[2 * idx] : ew[idx];
}

// ---------------- CSR build ----------------
__global__ void zero_wp() {
    int i = blockIdx.x * blockDim.x + threadIdx.x;
    if (i <= NN) g_wp[i] = 0;
}
__global__ void hist_k(const int* __restrict__ ew) {
    int i = blockIdx.x * blockDim.x + threadIdx.x;
    if (i >= ETOT) return;
    int d = (i < EG) ? edge_at(ew, (long long)EG + i) : (i - EG);
    atomicAdd(&g_wp[d], 1);
}
__global__ void part_k() {
    __shared__ int sm[256];
    int i = blockIdx.x * 256 + threadIdx.x;
    int v = (i < NN) ? g_wp[i] : 0;
    sm[threadIdx.x] = v;
    __syncthreads();
    for (int off = 128; off; off >>= 1) {
        if (threadIdx.x < off) sm[threadIdx.x] += sm[threadIdx.x + off];
        __syncthreads();
    }
    if (threadIdx.x == 0) g_bsum[blockIdx.x] = sm[0];
}
__global__ void bscan_k() {
    __shared__ int sm[512];
    int t = threadIdx.x;
    int v = (t < SCB) ? g_bsum[t] : 0;
    sm[t] = v;
    __syncthreads();
    for (int off = 1; off < 512; off <<= 1) {
        int u = (t >= off) ? sm[t - off] : 0;
        __syncthreads();
        sm[t] += u;
        __syncthreads();
    }
    if (t < SCB) g_bsum[t] = sm[t] - v;
}
__global__ void final_k() {
    __shared__ int sm[256];
    int b = blockIdx.x, t = threadIdx.x;
    int i = b * 256 + t;
    int v = (i < NN) ? g_wp[i] : 0;
    sm[t] = v;
    __syncthreads();
    for (int off = 1; off < 256; off <<= 1) {
        int u = (t >= off) ? sm[t - off] : 0;
        __syncthreads();
        sm[t] += u;
        __syncthreads();
    }
    int exc = g_bsum[b] + sm[t] - v;
    if (i < NN) { g_rowptr[i] = exc; g_wp[i] = exc; }
    if (i == NN - 1) g_rowptr[NN] = g_bsum[b] + sm[t];
}
__global__ void scatter_k(const int* __restrict__ ew) {
    int i = blockIdx.x * blockDim.x + threadIdx.x;
    if (i >= ETOT) return;
    int s, d;
    if (i < EG) { s = edge_at(ew, i); d = edge_at(ew, (long long)EG + i); }
    else { s = d = i - EG; }
    int pos = atomicAdd(&g_wp[d], 1);
    g_col[pos] = s;
}

// ---------------- split / transpose prep ----------------
__global__ void prepw_k(const float* __restrict__ W, int which, int K, int Nc) {
    int i = blockIdx.x * 256 + threadIdx.x;
    if (i >= K * Nc) return;
    int k = i / Nc, n = i % Nc;
    float v = W[i];
    __half h = __float2half(v);
    __half l = __float2half(v - __half2float(h));
    size_t o = (size_t)n * K + k;
    if (which == 0)      { g_w0t_hi[o] = h; g_w0t_lo[o] = l; }
    else if (which == 1) { g_w1t_hi[o] = h; g_w1t_lo[o] = l; }
    else                 { g_w2t_hi[o] = h; g_w2t_lo[o] = l; }
}
// vectorized fp16 convert: float4 in, 4 halves out per thread
__global__ void prepx_k(const float* __restrict__ x) {
    int i = blockIdx.x * 256 + threadIdx.x;       // quad index
    if (i >= (NN * NFEAT) / 4) return;
    float4 v = ((const float4*)x)[i];
    __half2 p01 = __floats2half2_rn(v.x, v.y);
    __half2 p23 = __floats2half2_rn(v.z, v.w);
    uint2 hp; hp.x = *(uint32_t*)&p01; hp.y = *(uint32_t*)&p23;
    ((uint2*)g_xa)[i] = hp;
}

// ---------------- fp16 HMMA GEMM: C[M,Nc] = A[M,K] @ Wt[Nc,K]^T ----------------
// Numerics: A single fp16; B = bh + bl fp16 split. D = a*bh + a*bl (2 MMAs).
// CTA tile 128x128, 16 warps (4m x 4n), warp tile 32x32, K-chunk 64.
// 2-stage cp.async pipeline; smem XOR-swizzled. Fused al_s/al_d epilogue.
#define STAGE_BYTES 49152      // 3 tiles x 16KB
#define SM_A    0
#define SM_B_HI 16384
#define SM_B_LO 32768
#define SM_ALS  (2 * STAGE_BYTES)
#define SM_ALD  (2 * STAGE_BYTES + 1024)
#define SMEM_MM (2 * STAGE_BYTES + 2048)

template <int LAYER>
__global__ void __launch_bounds__(512) mm_k(const float* __restrict__ asrc,
                                            const float* __restrict__ adst)
{
    constexpr int K  = (LAYER == 0) ? NFEAT : HID;
    constexpr int Nc = (LAYER == 2) ? NOUTF : HID;
    constexpr int NCH = K / 64;

    extern __shared__ char smem[];
    uint32_t sb = smem_u32(smem);
    float* sals = (float*)(smem + SM_ALS);
    float* sald = (float*)(smem + SM_ALD);

    int tid = threadIdx.x, w = tid >> 5, lane = tid & 31;
    int wm = w >> 2, wn = w & 3;          // 4m x 4n warp grid, warp tile 32x32
    int row0 = blockIdx.y * 128, colblk = blockIdx.x * 128;

    const __half* A   = (LAYER == 0) ? g_xa : g_fa;
    const __half* Bhi = (LAYER == 0) ? g_w0t_hi : (LAYER == 1) ? g_w1t_hi : g_w2t_hi;
    const __half* Blo = (LAYER == 0) ? g_w0t_lo : (LAYER == 1) ? g_w1t_lo : g_w2t_lo;

    if (tid < 256) { sals[tid] = 0.f; sald[tid] = 0.f; }

    // per-thread fill coordinates (2 x 16B per tile per thread; 1024 chunks/tile)
    int fr[2], fc[2];
    uint32_t fsw[2];
#pragma unroll
    for (int l = 0; l < 2; l++) {
        int f = tid + 512 * l;
        fr[l] = f >> 3; fc[l] = f & 7;
        fsw[l] = (uint32_t)fr[l] * 128 + (((uint32_t)(fc[l] ^ (fr[l] & 7))) << 4);
    }

    auto prefetch = [&](int ch, int stage) {
        uint32_t stb = sb + stage * STAGE_BYTES;
        int kk = ch * 64;
#pragma unroll
        for (int l = 0; l < 2; l++) {
            int r = fr[l], c = fc[l];
            int gr = row0 + r;
            uint32_t asz = (gr < NN) ? 16u : 0u;
            int gra = (gr < NN) ? gr : 0;
            cpasync16(stb + SM_A + fsw[l], A + (size_t)gra * K + kk + c * 8, asz);
            cpasync16(stb + SM_B_HI + fsw[l], Bhi + (size_t)(colblk + r) * K + kk + c * 8, 16u);
            cpasync16(stb + SM_B_LO + fsw[l], Blo + (size_t)(colblk + r) * K + kk + c * 8, 16u);
        }
        CP_COMMIT();
    };

    float acc[2][4][4];
#pragma unroll
    for (int mf = 0; mf < 2; mf++)
#pragma unroll
        for (int nf = 0; nf < 4; nf++)
#pragma unroll
            for (int j = 0; j < 4; j++) acc[mf][nf][j] = 0.f;

    prefetch(0, 0);

    for (int ch = 0; ch < NCH; ch++) {
        int stage = ch & 1;
        if (ch + 1 < NCH) {
            prefetch(ch + 1, (ch + 1) & 1);
            CP_WAIT(1);            // stage `ch` complete; ch+1 still in flight
        } else {
            CP_WAIT(0);
        }
        __syncthreads();

        uint32_t stb = sb + stage * STAGE_BYTES;
#pragma unroll
        for (int s = 0; s < 4; s++) {
            uint32_t af[2][4], bh[4][2], bl[4][2];
            // A fragments (x4): lanes 0-7 m0, 8-15 m1(+8 rows), 16-23 m2(+16B k), 24-31 m3
            int rsel = (lane & 7) + ((lane >> 3) & 1) * 8;
            int kca = 2 * s + (lane >> 4);
#pragma unroll
            for (int mf = 0; mf < 2; mf++) {
                int row = wm * 32 + mf * 16 + rsel;
                uint32_t off = (uint32_t)row * 128 + (((uint32_t)(kca ^ (row & 7))) << 4);
                ldmx4(af[mf], stb + SM_A + off);
            }
            // B fragments: one x4 covers 2 n-tiles x 2 k-halves.
            // lane groups: 0-7 -> (nf even, k0), 8-15 -> (nf even, k1),
            //              16-23 -> (nf odd, k0), 24-31 -> (nf odd, k1)
            int g = lane >> 3;                      // 0..3
            int brow_sub = ((g >> 1) << 3) + (lane & 7);
            int kcb = 2 * s + (g & 1);
#pragma unroll
            for (int nfp = 0; nfp < 2; nfp++) {
                int nrow = wn * 32 + nfp * 16 + brow_sub;
                uint32_t off = (uint32_t)nrow * 128 + (((uint32_t)(kcb ^ (nrow & 7))) << 4);
                uint32_t rh[4], rl[4];
                ldmx4(rh, stb + SM_B_HI + off);
                ldmx4(rl, stb + SM_B_LO + off);
                bh[nfp * 2 + 0][0] = rh[0]; bh[nfp * 2 + 0][1] = rh[1];
                bh[nfp * 2 + 1][0] = rh[2]; bh[nfp * 2 + 1][1] = rh[3];
                bl[nfp * 2 + 0][0] = rl[0]; bl[nfp * 2 + 0][1] = rl[1];
                bl[nfp * 2 + 1][0] = rl[2]; bl[nfp * 2 + 1][1] = rl[3];
            }
#pragma unroll
            for (int mf = 0; mf < 2; mf++)
#pragma unroll
                for (int nf = 0; nf < 4; nf++) {
                    mma16816h(acc[mf][nf], af[mf], bh[nf]);
                    mma16816h(acc[mf][nf], af[mf], bl[nf]);
                }
        }
        __syncthreads();   // all reads of this stage done before it's refilled
    }

    // epilogue: write C (fp32) + fused al_s/al_d row dots
    int hl = wn >> 1;      // head-local: cols [0,64) -> 0, [64,128) -> 1
#pragma unroll
    for (int mf = 0; mf < 2; mf++) {
        int lr0 = wm * 32 + mf * 16 + (lane >> 2);
        int row_a = row0 + lr0;
        int row_b = row_a + 8;
        float ps0 = 0.f, pd0 = 0.f, ps8 = 0.f, pd8 = 0.f;
#pragma unroll
        for (int nf = 0; nf < 4; nf++) {
            float* c = acc[mf][nf];
            int colg = colblk + wn * 32 + nf * 8 + (lane & 3) * 2;
            if (row_a < NN) *(float2*)(g_h + (size_t)row_a * Nc + colg) = make_float2(c[0], c[1]);
            if (row_b < NN) *(float2*)(g_h + (size_t)row_b * Nc + colg) = make_float2(c[2], c[3]);
            float w0s = asrc[colg], w1s = asrc[colg + 1];
            float w0d = adst[colg], w1d = adst[colg + 1];
            ps0 += c[0] * w0s + c[1] * w1s; pd0 += c[0] * w0d + c[1] * w1d;
            ps8 += c[2] * w0s + c[3] * w1s; pd8 += c[2] * w0d + c[3] * w1d;
        }
#pragma unroll
        for (int off = 1; off <= 2; off <<= 1) {
            ps0 += __shfl_xor_sync(0xffffffffu, ps0, off);
            pd0 += __shfl_xor_sync(0xffffffffu, pd0, off);
            ps8 += __shfl_xor_sync(0xffffffffu, ps8, off);
            pd8 += __shfl_xor_sync(0xffffffffu, pd8, off);
        }
        if ((lane & 3) == 0) {
            atomicAdd(&sals[lr0 * 2 + hl], ps0);
            atomicAdd(&sald[lr0 * 2 + hl], pd0);
            atomicAdd(&sals[(lr0 + 8) * 2 + hl], ps8);
            atomicAdd(&sald[(lr0 + 8) * 2 + hl], pd8);
        }
    }
    __syncthreads();

    if (LAYER == 2) {
        if (tid < 128) {
            int row = row0 + tid;
            if (row < NN) {
                g_als[row] = sals[tid * 2] + sals[tid * 2 + 1];
                g_ald[row] = sald[tid * 2] + sald[tid * 2 + 1];
            }
        }
    } else {
        if (tid < 256) {
            int lr = tid >> 1, h = tid & 1;
            int row = row0 + lr;
            int head = blockIdx.x * 2 + h;
            if (row < NN) {
                g_als[row * 4 + head] = sals[tid];
                g_ald[row * 4 + head] = sald[tid];
            }
        }
    }
}

// ---------------- fused softmax + aggregation + bias (+ELU), warp per dst node ----------------
template <int H, int C, bool ELU, int OUT_MODE>   // OUT_MODE 0: fp16 feat; 1: fp32 out
__global__ void __launch_bounds__(256) agg_k(
    const float* __restrict__ bias, float* __restrict__ outp)
{
    constexpr int HC = H * C;
    constexpr int V = HC / 128;
    int nd = (blockIdx.x * blockDim.x + threadIdx.x) >> 5;
    int lane = threadIdx.x & 31;
    if (nd >= NN) return;
    int beg = g_rowptr[nd], end = g_rowptr[nd + 1];

    float aldv = (lane < H) ? g_ald[nd * H + lane] : 0.f;

    float4 acc[V];
#pragma unroll
    for (int v = 0; v < V; v++) acc[v] = make_float4(0.f, 0.f, 0.f, 0.f);
    float denom = 0.f;

    for (int e = beg; e < end; e++) {
        int s = g_col[e];
        float exh = 0.f;
        if (lane < H) {
            float ev = g_als[s * H + lane] + aldv;
            ev = ev > 0.f ? ev : 0.2f * ev;
            exh = __expf(ev);
            denom += exh;
        }
        const float4* hv = (const float4*)(g_h + (size_t)s * HC);
#pragma unroll
        for (int v = 0; v < V; v++) {
            int c4 = lane + 32 * v;
            int head = (4 * c4) / C;
            float a = __shfl_sync(0xffffffffu, exh, head);
            float4 xv = hv[c4];
            acc[v].x += a * xv.x;
            acc[v].y += a * xv.y;
            acc[v].z += a * xv.z;
            acc[v].w += a * xv.w;
        }
    }

#pragma unroll
    for (int v = 0; v < V; v++) {
        int c4 = lane + 32 * v;
        int head = (4 * c4) / C;
        float den = __shfl_sync(0xffffffffu, denom, head) + 1e-16f;
        float inv = 1.f / den;
        float4 b4 = ((const float4*)bias)[c4];
        float4 o;
        o.x = acc[v].x * inv + b4.x;
        o.y = acc[v].y * inv + b4.y;
        o.z = acc[v].z * inv + b4.z;
        o.w = acc[v].w * inv + b4.w;
        if (ELU) {
            o.x = o.x > 0.f ? o.x : expm1f(o.x);
            o.y = o.y > 0.f ? o.y : expm1f(o.y);
            o.z = o.z > 0.f ? o.z : expm1f(o.z);
            o.w = o.w > 0.f ? o.w : expm1f(o.w);
        }
        if (OUT_MODE == 1) {
            ((float4*)(outp + (size_t)nd * HC))[c4] = o;
        } else {
            __half2 p01 = __floats2half2_rn(o.x, o.y);
            __half2 p23 = __floats2half2_rn(o.z, o.w);
            uint2 hp;
            hp.x = *(uint32_t*)&p01; hp.y = *(uint32_t*)&p23;
            ((uint2*)(g_fa + (size_t)nd * HC))[c4] = hp;
        }
    }
}

// ---------------- launch ----------------
extern "C" void kernel_launch(void* const* d_in, const int* in_sizes, int n_in,
                              void* d_out, int out_size)
{
    const float* x   = (const float*)d_in[0];
    const int*   ew  = (const int*)d_in[1];
    const float* W0  = (const float*)d_in[2];
    const float* as0 = (const float*)d_in[3];
    const float* ad0 = (const float*)d_in[4];
    const float* b0  = (const float*)d_in[5];
    const float* W1  = (const float*)d_in[6];
    const float* as1 = (const float*)d_in[7];
    const float* ad1 = (const float*)d_in[8];
    const float* b1  = (const float*)d_in[9];
    const float* W2  = (const float*)d_in[10];
    const float* as2 = (const float*)d_in[11];
    const float* ad2 = (const float*)d_in[12];
    const float* b2  = (const float*)d_in[13];
    float* out = (float*)d_out;

    cudaFuncSetAttribute(mm_k<0>, cudaFuncAttributeMaxDynamicSharedMemorySize, SMEM_MM);
    cudaFuncSetAttribute(mm_k<1>, cudaFuncAttributeMaxDynamicSharedMemorySize, SMEM_MM);
    cudaFuncSetAttribute(mm_k<2>, cudaFuncAttributeMaxDynamicSharedMemorySize, SMEM_MM);

    int warp_blocks = (NN * 32 + 255) / 256;
    int mtiles = (NN + 127) / 128;

    // launches 1-3: prep needed by mm_k<0>; launch 4 = mm_k<0> (ncu captures launch #4)
    prepw_k<<<(NFEAT * HID + 255) / 256, 256>>>(W0, 0, NFEAT, HID);
    prepx_k<<<((NN * NFEAT / 4) + 255) / 256, 256>>>(x);
    prepw_k<<<(HID * HID + 255) / 256, 256>>>(W1, 1, HID, HID);
    mm_k<0><<<dim3(2, mtiles), 512, SMEM_MM>>>(as0, ad0);

    // remaining prep + CSR build
    prepw_k<<<(HID * NOUTF + 255) / 256, 256>>>(W2, 2, HID, NOUTF);
    detect_k<<<1, 1>>>(ew);
    zero_wp<<<(NN + 256) / 256, 256>>>();
    hist_k<<<(ETOT + 255) / 256, 256>>>(ew);
    part_k<<<SCB, 256>>>();
    bscan_k<<<1, 512>>>();
    final_k<<<SCB, 256>>>();
    scatter_k<<<(ETOT + 255) / 256, 256>>>(ew);

    // layer 0 aggregation
    agg_k<4, 64, true, 0><<<warp_blocks, 256>>>(b0, nullptr);
    // layer 1
    mm_k<1><<<dim3(2, mtiles), 512, SMEM_MM>>>(as1, ad1);
    agg_k<4, 64, true, 0><<<warp_blocks, 256>>>(b1, nullptr);
    // layer 2
    mm_k<2><<<dim3(1, mtiles), 512, SMEM_MM>>>(as2, ad2);
    agg_k<1, 128, false, 1><<<warp_blocks, 256>>>(b2, out);
}

// round 15
// speedup vs baseline: 1.0116x; 1.0116x over previous
#include <cuda_runtime.h>
#include <cuda_fp16.h>
#include <math.h>
#include <cstdint>

#define NN 100000
#define EG 400000
#define NFEAT 128
#define HID 256
#define NOUTF 128
#define ETOT (EG + NN)
#define SCB ((NN + 255) / 256)

// ---------------- scratch (device globals; no allocation allowed) ----------------
__device__ float g_h[(size_t)NN * HID];            // transformed features h (fp32)
__device__ __half g_xa[(size_t)NN * NFEAT];        // input features, fp16
__device__ __half g_fa[(size_t)NN * HID];          // layer activations, fp16
__device__ __half g_w0t_hi[HID * NFEAT], g_w0t_lo[HID * NFEAT];   // [N][K] fp16 split
__device__ __half g_w1t_hi[HID * HID],   g_w1t_lo[HID * HID];
__device__ __half g_w2t_hi[NOUTF * HID], g_w2t_lo[NOUTF * HID];
__device__ float g_als[NN * 4];
__device__ float g_ald[NN * 4];
__device__ int   g_rowptr[NN + 1];
__device__ int   g_wp[NN + 1];
__device__ int   g_bsum[SCB + 1];
__device__ int   g_col[ETOT];
__device__ int   g_is64;

// ---------------- warp-MMA helpers (portable PTX, sm_80+) ----------------
__device__ __forceinline__ uint32_t smem_u32(const void* p) {
    uint32_t a;
    asm("{ .reg .u64 t; cvta.to.shared.u64 t, %1; cvt.u32.u64 %0, t; }" : "=r"(a) : "l"(p));
    return a;
}
__device__ __forceinline__ void ldmx4(uint32_t* r, uint32_t addr) {
    asm volatile("ldmatrix.sync.aligned.m8n8.x4.shared.b16 {%0,%1,%2,%3}, [%4];"
                 : "=r"(r[0]), "=r"(r[1]), "=r"(r[2]), "=r"(r[3]) : "r"(addr));
}
__device__ __forceinline__ void mma16816h(float* c, const uint32_t* a, const uint32_t* b) {
    asm volatile("mma.sync.aligned.m16n8k16.row.col.f32.f16.f16.f32 "
                 "{%0,%1,%2,%3}, {%4,%5,%6,%7}, {%8,%9}, {%0,%1,%2,%3};"
                 : "+f"(c[0]), "+f"(c[1]), "+f"(c[2]), "+f"(c[3])
                 : "r"(a[0]), "r"(a[1]), "r"(a[2]), "r"(a[3]), "r"(b[0]), "r"(b[1]));
}
__device__ __forceinline__ void cpasync16(uint32_t saddr, const void* gptr, uint32_t srcsz) {
    asm volatile("cp.async.cg.shared.global [%0], [%1], 16, %2;"
                 :: "r"(saddr), "l"(gptr), "r"(srcsz) : "memory");
}
#define CP_COMMIT() asm volatile("cp.async.commit_group;" ::: "memory")
#define CP_WAIT(n)  asm volatile("cp.async.wait_group %0;" :: "n"(n) : "memory")

// ---------------- edge dtype sniffer ----------------
__global__ void detect_k(const int* __restrict__ ew) {
    int all_zero = 1;
    for (int i = 0; i < 64; i++)
        if (ew[2 * i + 1] != 0) { all_zero = 0; break; }
    g_is64 = all_zero;
}
__device__ __forceinline__ int edge_at(const int* ew, long long idx) {
    return g_is64 ? ew[2 * idx] : ew[idx];
}

// ---------------- CSR build ----------------
__global__ void zero_wp() {
    int i = blockIdx.x * blockDim.x + threadIdx.x;
    if (i <= NN) g_wp[i] = 0;
}
__global__ void hist_k(const int* __restrict__ ew) {
    int i = blockIdx.x * blockDim.x + threadIdx.x;
    if (i >= ETOT) return;
    int d = (i < EG) ? edge_at(ew, (long long)EG + i) : (i - EG);
    atomicAdd(&g_wp[d], 1);
}
__global__ void part_k() {
    __shared__ int sm[256];
    int i = blockIdx.x * 256 + threadIdx.x;
    int v = (i < NN) ? g_wp[i] : 0;
    sm[threadIdx.x] = v;
    __syncthreads();
    for (int off = 128; off; off >>= 1) {
        if (threadIdx.x < off) sm[threadIdx.x] += sm[threadIdx.x + off];
        __syncthreads();
    }
    if (threadIdx.x == 0) g_bsum[blockIdx.x] = sm[0];
}
__global__ void bscan_k() {
    __shared__ int sm[512];
    int t = threadIdx.x;
    int v = (t < SCB) ? g_bsum[t] : 0;
    sm[t] = v;
    __syncthreads();
    for (int off = 1; off < 512; off <<= 1) {
        int u = (t >= off) ? sm[t - off] : 0;
        __syncthreads();
        sm[t] += u;
        __syncthreads();
    }
    if (t < SCB) g_bsum[t] = sm[t] - v;
}
__global__ void final_k() {
    __shared__ int sm[256];
    int b = blockIdx.x, t = threadIdx.x;
    int i = b * 256 + t;
    int v = (i < NN) ? g_wp[i] : 0;
    sm[t] = v;
    __syncthreads();
    for (int off = 1; off < 256; off <<= 1) {
        int u = (t >= off) ? sm[t - off] : 0;
        __syncthreads();
        sm[t] += u;
        __syncthreads();
    }
    int exc = g_bsum[b] + sm[t] - v;
    if (i < NN) { g_rowptr[i] = exc; g_wp[i] = exc; }
    if (i == NN - 1) g_rowptr[NN] = g_bsum[b] + sm[t];
}
__global__ void scatter_k(const int* __restrict__ ew) {
    int i = blockIdx.x * blockDim.x + threadIdx.x;
    if (i >= ETOT) return;
    int s, d;
    if (i < EG) { s = edge_at(ew, i); d = edge_at(ew, (long long)EG + i); }
    else { s = d = i - EG; }
    int pos = atomicAdd(&g_wp[d], 1);
    g_col[pos] = s;
}

// ---------------- split / transpose prep ----------------
__global__ void prepw_k(const float* __restrict__ W, int which, int K, int Nc) {
    int i = blockIdx.x * 256 + threadIdx.x;
    if (i >= K * Nc) return;
    int k = i / Nc, n = i % Nc;
    float v = W[i];
    __half h = __float2half(v);
    __half l = __float2half(v - __half2float(h));
    size_t o = (size_t)n * K + k;
    if (which == 0)      { g_w0t_hi[o] = h; g_w0t_lo[o] = l; }
    else if (which == 1) { g_w1t_hi[o] = h; g_w1t_lo[o] = l; }
    else                 { g_w2t_hi[o] = h; g_w2t_lo[o] = l; }
}
// vectorized fp16 convert: float4 in, 4 halves out per thread
__global__ void prepx_k(const float* __restrict__ x) {
    int i = blockIdx.x * 256 + threadIdx.x;       // quad index
    if (i >= (NN * NFEAT) / 4) return;
    float4 v = ((const float4*)x)[i];
    __half2 p01 = __floats2half2_rn(v.x, v.y);
    __half2 p23 = __floats2half2_rn(v.z, v.w);
    uint2 hp; hp.x = *(uint32_t*)&p01; hp.y = *(uint32_t*)&p23;
    ((uint2*)g_xa)[i] = hp;
}

// ---------------- fp16 HMMA GEMM: C[M,Nc] = A[M,K] @ Wt[Nc,K]^T ----------------
// Numerics: A single fp16; B = bh + bl fp16 split. D = a*bh + a*bl (2 MMAs).
// CTA tile 128x128, 16 warps (4m x 4n), warp tile 32x32, K-chunk 64.
// 2-stage cp.async pipeline; smem XOR-swizzled. Fused al_s/al_d epilogue.
#define STAGE_BYTES 49152      // 3 tiles x 16KB
#define SM_A    0
#define SM_B_HI 16384
#define SM_B_LO 32768
#define SM_ALS  (2 * STAGE_BYTES)
#define SM_ALD  (2 * STAGE_BYTES + 1024)
#define SMEM_MM (2 * STAGE_BYTES + 2048)

template <int LAYER>
__global__ void __launch_bounds__(512) mm_k(const float* __restrict__ asrc,
                                            const float* __restrict__ adst)
{
    constexpr int K  = (LAYER == 0) ? NFEAT : HID;
    constexpr int Nc = (LAYER == 2) ? NOUTF : HID;
    constexpr int NCH = K / 64;

    extern __shared__ char smem[];
    uint32_t sb = smem_u32(smem);
    float* sals = (float*)(smem + SM_ALS);
    float* sald = (float*)(smem + SM_ALD);

    int tid = threadIdx.x, w = tid >> 5, lane = tid & 31;
    int wm = w >> 2, wn = w & 3;          // 4m x 4n warp grid, warp tile 32x32
    int row0 = blockIdx.y * 128, colblk = blockIdx.x * 128;

    const __half* A   = (LAYER == 0) ? g_xa : g_fa;
    const __half* Bhi = (LAYER == 0) ? g_w0t_hi : (LAYER == 1) ? g_w1t_hi : g_w2t_hi;
    const __half* Blo = (LAYER == 0) ? g_w0t_lo : (LAYER == 1) ? g_w1t_lo : g_w2t_lo;

    if (tid < 256) { sals[tid] = 0.f; sald[tid] = 0.f; }

    // per-thread fill coordinates (2 x 16B per tile per thread; 1024 chunks/tile)
    int fr[2], fc[2];
    uint32_t fsw[2];
#pragma unroll
    for (int l = 0; l < 2; l++) {
        int f = tid + 512 * l;
        fr[l] = f >> 3; fc[l] = f & 7;
        fsw[l] = (uint32_t)fr[l] * 128 + (((uint32_t)(fc[l] ^ (fr[l] & 7))) << 4);
    }

    auto prefetch = [&](int ch, int stage) {
        uint32_t stb = sb + stage * STAGE_BYTES;
        int kk = ch * 64;
#pragma unroll
        for (int l = 0; l < 2; l++) {
            int r = fr[l], c = fc[l];
            int gr = row0 + r;
            uint32_t asz = (gr < NN) ? 16u : 0u;
            int gra = (gr < NN) ? gr : 0;
            cpasync16(stb + SM_A + fsw[l], A + (size_t)gra * K + kk + c * 8, asz);
            cpasync16(stb + SM_B_HI + fsw[l], Bhi + (size_t)(colblk + r) * K + kk + c * 8, 16u);
            cpasync16(stb + SM_B_LO + fsw[l], Blo + (size_t)(colblk + r) * K + kk + c * 8, 16u);
        }
        CP_COMMIT();
    };

    float acc[2][4][4];
#pragma unroll
    for (int mf = 0; mf < 2; mf++)
#pragma unroll
        for (int nf = 0; nf < 4; nf++)
#pragma unroll
            for (int j = 0; j < 4; j++) acc[mf][nf][j] = 0.f;

    prefetch(0, 0);

    for (int ch = 0; ch < NCH; ch++) {
        int stage = ch & 1;
        if (ch + 1 < NCH) {
            prefetch(ch + 1, (ch + 1) & 1);
            CP_WAIT(1);            // stage `ch` complete; ch+1 still in flight
        } else {
            CP_WAIT(0);
        }
        __syncthreads();

        uint32_t stb = sb + stage * STAGE_BYTES;
#pragma unroll
        for (int s = 0; s < 4; s++) {
            uint32_t af[2][4], bh[4][2], bl[4][2];
            // A fragments (x4): lanes 0-7 m0, 8-15 m1(+8 rows), 16-23 m2(+16B k), 24-31 m3
            int rsel = (lane & 7) + ((lane >> 3) & 1) * 8;
            int kca = 2 * s + (lane >> 4);
#pragma unroll
            for (int mf = 0; mf < 2; mf++) {
                int row = wm * 32 + mf * 16 + rsel;
                uint32_t off = (uint32_t)row * 128 + (((uint32_t)(kca ^ (row & 7))) << 4);
                ldmx4(af[mf], stb + SM_A + off);
            }
            // B fragments: one x4 covers 2 n-tiles x 2 k-halves.
            // lane groups: 0-7 -> (nf even, k0), 8-15 -> (nf even, k1),
            //              16-23 -> (nf odd, k0), 24-31 -> (nf odd, k1)
            int g = lane >> 3;                      // 0..3
            int brow_sub = ((g >> 1) << 3) + (lane & 7);
            int kcb = 2 * s + (g & 1);
#pragma unroll
            for (int nfp = 0; nfp < 2; nfp++) {
                int nrow = wn * 32 + nfp * 16 + brow_sub;
                uint32_t off = (uint32_t)nrow * 128 + (((uint32_t)(kcb ^ (nrow & 7))) << 4);
                uint32_t rh[4], rl[4];
                ldmx4(rh, stb + SM_B_HI + off);
                ldmx4(rl, stb + SM_B_LO + off);
                bh[nfp * 2 + 0][0] = rh[0]; bh[nfp * 2 + 0][1] = rh[1];
                bh[nfp * 2 + 1][0] = rh[2]; bh[nfp * 2 + 1][1] = rh[3];
                bl[nfp * 2 + 0][0] = rl[0]; bl[nfp * 2 + 0][1] = rl[1];
                bl[nfp * 2 + 1][0] = rl[2]; bl[nfp * 2 + 1][1] = rl[3];
            }
#pragma unroll
            for (int mf = 0; mf < 2; mf++)
#pragma unroll
                for (int nf = 0; nf < 4; nf++) {
                    mma16816h(acc[mf][nf], af[mf], bh[nf]);
                    mma16816h(acc[mf][nf], af[mf], bl[nf]);
                }
        }
        __syncthreads();   // all reads of this stage done before it's refilled
    }

    // epilogue: write C (fp32) + fused al_s/al_d row dots
    int hl = wn >> 1;      // head-local: cols [0,64) -> 0, [64,128) -> 1
#pragma unroll
    for (int mf = 0; mf < 2; mf++) {
        int lr0 = wm * 32 + mf * 16 + (lane >> 2);
        int row_a = row0 + lr0;
        int row_b = row_a + 8;
        float ps0 = 0.f, pd0 = 0.f, ps8 = 0.f, pd8 = 0.f;
#pragma unroll
        for (int nf = 0; nf < 4; nf++) {
            float* c = acc[mf][nf];
            int colg = colblk + wn * 32 + nf * 8 + (lane & 3) * 2;
            if (row_a < NN) *(float2*)(g_h + (size_t)row_a * Nc + colg) = make_float2(c[0], c[1]);
            if (row_b < NN) *(float2*)(g_h + (size_t)row_b * Nc + colg) = make_float2(c[2], c[3]);
            float w0s = asrc[colg], w1s = asrc[colg + 1];
            float w0d = adst[colg], w1d = adst[colg + 1];
            ps0 += c[0] * w0s + c[1] * w1s; pd0 += c[0] * w0d + c[1] * w1d;
            ps8 += c[2] * w0s + c[3] * w1s; pd8 += c[2] * w0d + c[3] * w1d;
        }
#pragma unroll
        for (int off = 1; off <= 2; off <<= 1) {
            ps0 += __shfl_xor_sync(0xffffffffu, ps0, off);
            pd0 += __shfl_xor_sync(0xffffffffu, pd0, off);
            ps8 += __shfl_xor_sync(0xffffffffu, ps8, off);
            pd8 += __shfl_xor_sync(0xffffffffu, pd8, off);
        }
        if ((lane & 3) == 0) {
            atomicAdd(&sals[lr0 * 2 + hl], ps0);
            atomicAdd(&sald[lr0 * 2 + hl], pd0);
            atomicAdd(&sals[(lr0 + 8) * 2 + hl], ps8);
            atomicAdd(&sald[(lr0 + 8) * 2 + hl], pd8);
        }
    }
    __syncthreads();

    if (LAYER == 2) {
        if (tid < 128) {
            int row = row0 + tid;
            if (row < NN) {
                g_als[row] = sals[tid * 2] + sals[tid * 2 + 1];
                g_ald[row] = sald[tid * 2] + sald[tid * 2 + 1];
            }
        }
    } else {
        if (tid < 256) {
            int lr = tid >> 1, h = tid & 1;
            int row = row0 + lr;
            int head = blockIdx.x * 2 + h;
            if (row < NN) {
                g_als[row * 4 + head] = sals[tid];
                g_ald[row * 4 + head] = sald[tid];
            }
        }
    }
}

// ---------------- fused softmax + aggregation + bias (+ELU), warp per dst node ----------------
template <int H, int C, bool ELU, int OUT_MODE>   // OUT_MODE 0: fp16 feat; 1: fp32 out
__global__ void __launch_bounds__(256) agg_k(
    const float* __restrict__ bias, float* __restrict__ outp)
{
    constexpr int HC = H * C;
    constexpr int V = HC / 128;
    int nd = (blockIdx.x * blockDim.x + threadIdx.x) >> 5;
    int lane = threadIdx.x & 31;
    if (nd >= NN) return;
    int beg = g_rowptr[nd], end = g_rowptr[nd + 1];

    float aldv = (lane < H) ? g_ald[nd * H + lane] : 0.f;

    float4 acc[V];
#pragma unroll
    for (int v = 0; v < V; v++) acc[v] = make_float4(0.f, 0.f, 0.f, 0.f);
    float denom = 0.f;

    for (int e = beg; e < end; e++) {
        int s = g_col[e];
        float exh = 0.f;
        if (lane < H) {
            float ev = g_als[s * H + lane] + aldv;
            ev = ev > 0.f ? ev : 0.2f * ev;
            exh = __expf(ev);
            denom += exh;
        }
        const float4* hv = (const float4*)(g_h + (size_t)s * HC);
#pragma unroll
        for (int v = 0; v < V; v++) {
            int c4 = lane + 32 * v;
            int head = (4 * c4) / C;
            float a = __shfl_sync(0xffffffffu, exh, head);
            float4 xv = hv[c4];
            acc[v].x += a * xv.x;
            acc[v].y += a * xv.y;
            acc[v].z += a * xv.z;
            acc[v].w += a * xv.w;
        }
    }

#pragma unroll
    for (int v = 0; v < V; v++) {
        int c4 = lane + 32 * v;
        int head = (4 * c4) / C;
        float den = __shfl_sync(0xffffffffu, denom, head) + 1e-16f;
        float inv = 1.f / den;
        float4 b4 = ((const float4*)bias)[c4];
        float4 o;
        o.x = acc[v].x * inv + b4.x;
        o.y = acc[v].y * inv + b4.y;
        o.z = acc[v].z * inv + b4.z;
        o.w = acc[v].w * inv + b4.w;
        if (ELU) {
            o.x = o.x > 0.f ? o.x : expm1f(o.x);
            o.y = o.y > 0.f ? o.y : expm1f(o.y);
            o.z = o.z > 0.f ? o.z : expm1f(o.z);
            o.w = o.w > 0.f ? o.w : expm1f(o.w);
        }
        if (OUT_MODE == 1) {
            ((float4*)(outp + (size_t)nd * HC))[c4] = o;
        } else {
            __half2 p01 = __floats2half2_rn(o.x, o.y);
            __half2 p23 = __floats2half2_rn(o.z, o.w);
            uint2 hp;
            hp.x = *(uint32_t*)&p01; hp.y = *(uint32_t*)&p23;
            ((uint2*)(g_fa + (size_t)nd * HC))[c4] = hp;
        }
    }
}

// ---------------- launch ----------------
extern "C" void kernel_launch(void* const* d_in, const int* in_sizes, int n_in,
                              void* d_out, int out_size)
{
    const float* x   = (const float*)d_in[0];
    const int*   ew  = (const int*)d_in[1];
    const float* W0  = (const float*)d_in[2];
    const float* as0 = (const float*)d_in[3];
    const float* ad0 = (const float*)d_in[4];
    const float* b0  = (const float*)d_in[5];
    const float* W1  = (const float*)d_in[6];
    const float* as1 = (const float*)d_in[7];
    const float* ad1 = (const float*)d_in[8];
    const float* b1  = (const float*)d_in[9];
    const float* W2  = (const float*)d_in[10];
    const float* as2 = (const float*)d_in[11];
    const float* ad2 = (const float*)d_in[12];
    const float* b2  = (const float*)d_in[13];
    float* out = (float*)d_out;

    cudaFuncSetAttribute(mm_k<0>, cudaFuncAttributeMaxDynamicSharedMemorySize, SMEM_MM);
    cudaFuncSetAttribute(mm_k<1>, cudaFuncAttributeMaxDynamicSharedMemorySize, SMEM_MM);
    cudaFuncSetAttribute(mm_k<2>, cudaFuncAttributeMaxDynamicSharedMemorySize, SMEM_MM);

    int warp_blocks = (NN * 32 + 255) / 256;
    int mtiles = (NN + 127) / 128;

    // launches 1-3: prep needed by mm_k<0>; launch 4 = mm_k<0> (ncu captures launch #4)
    prepw_k<<<(NFEAT * HID + 255) / 256, 256>>>(W0, 0, NFEAT, HID);
    prepx_k<<<((NN * NFEAT / 4) + 255) / 256, 256>>>(x);
    prepw_k<<<(HID * HID + 255) / 256, 256>>>(W1, 1, HID, HID);
    mm_k<0><<<dim3(2, mtiles), 512, SMEM_MM>>>(as0, ad0);

    // remaining prep + CSR build
    prepw_k<<<(HID * NOUTF + 255) / 256, 256>>>(W2, 2, HID, NOUTF);
    detect_k<<<1, 1>>>(ew);
    zero_wp<<<(NN + 256) / 256, 256>>>();
    hist_k<<<(ETOT + 255) / 256, 256>>>(ew);
    part_k<<<SCB, 256>>>();
    bscan_k<<<1, 512>>>();
    final_k<<<SCB, 256>>>();
    scatter_k<<<(ETOT + 255) / 256, 256>>>(ew);

    // layer 0 aggregation
    agg_k<4, 64, true, 0><<<warp_blocks, 256>>>(b0, nullptr);
    // layer 1
    mm_k<1><<<dim3(2, mtiles), 512, SMEM_MM>>>(as1, ad1);
    agg_k<4, 64, true, 0><<<warp_blocks, 256>>>(b1, nullptr);
    // layer 2
    mm_k<2><<<dim3(1, mtiles), 512, SMEM_MM>>>(as2, ad2);
    agg_k<1, 128, false, 1><<<warp_blocks, 256>>>(b2, out);
}

// round 16
// speedup vs baseline: 1.1363x; 1.1232x over previous
#include <cuda_runtime.h>
#include <cuda_fp16.h>
#include <math.h>
#include <cstdint>

#define NN 100000
#define EG 400000
#define NFEAT 128
#define HID 256
#define NOUTF 128
#define ETOT (EG + NN)
#define SCB ((NN + 255) / 256)

// ---------------- scratch (device globals; no allocation allowed) ----------------
__device__ __half g_h[(size_t)NN * HID];           // transformed features h (fp16)
__device__ __half g_xa[(size_t)NN * NFEAT];        // input features, fp16
__device__ __half g_fa[(size_t)NN * HID];          // layer activations, fp16
__device__ __half g_w0t_hi[HID * NFEAT], g_w0t_lo[HID * NFEAT];   // [N][K] fp16 split
__device__ __half g_w1t_hi[HID * HID],   g_w1t_lo[HID * HID];
__device__ __half g_w2t_hi[NOUTF * HID], g_w2t_lo[NOUTF * HID];
__device__ float g_als[NN * 4];
__device__ float g_ald[NN * 4];
__device__ int   g_rowptr[NN + 1];
__device__ int   g_wp[NN + 1];
__device__ int   g_bsum[SCB + 1];
__device__ int   g_col[ETOT];
__device__ int   g_is64;

// ---------------- warp-MMA helpers (portable PTX, sm_80+) ----------------
__device__ __forceinline__ uint32_t smem_u32(const void* p) {
    uint32_t a;
    asm("{ .reg .u64 t; cvta.to.shared.u64 t, %1; cvt.u32.u64 %0, t; }" : "=r"(a) : "l"(p));
    return a;
}
__device__ __forceinline__ void ldmx4(uint32_t* r, uint32_t addr) {
    asm volatile("ldmatrix.sync.aligned.m8n8.x4.shared.b16 {%0,%1,%2,%3}, [%4];"
                 : "=r"(r[0]), "=r"(r[1]), "=r"(r[2]), "=r"(r[3]) : "r"(addr));
}
__device__ __forceinline__ void mma16816h(float* c, const uint32_t* a, const uint32_t* b) {
    asm volatile("mma.sync.aligned.m16n8k16.row.col.f32.f16.f16.f32 "
                 "{%0,%1,%2,%3}, {%4,%5,%6,%7}, {%8,%9}, {%0,%1,%2,%3};"
                 : "+f"(c[0]), "+f"(c[1]), "+f"(c[2]), "+f"(c[3])
                 : "r"(a[0]), "r"(a[1]), "r"(a[2]), "r"(a[3]), "r"(b[0]), "r"(b[1]));
}
__device__ __forceinline__ void cpasync16(uint32_t saddr, const void* gptr, uint32_t srcsz) {
    asm volatile("cp.async.cg.shared.global [%0], [%1], 16, %2;"
                 :: "r"(saddr), "l"(gptr), "r"(srcsz) : "memory");
}
#define CP_COMMIT() asm volatile("cp.async.commit_group;" ::: "memory")
#define CP_WAIT(n)  asm volatile("cp.async.wait_group %0;" :: "n"(n) : "memory")

// ---------------- edge dtype sniffer ----------------
__global__ void detect_k(const int* __restrict__ ew) {
    int all_zero = 1;
    for (int i = 0; i < 64; i++)
        if (ew[2 * i + 1] != 0) { all_zero = 0; break; }
    g_is64 = all_zero;
}
__device__ __forceinline__ int edge_at(const int* ew, long long idx) {
    return g_is64 ? ew[2 * idx] : ew[idx];
}

// ---------------- CSR build ----------------
__global__ void zero_wp() {
    int i = blockIdx.x * blockDim.x + threadIdx.x;
    if (i <= NN) g_wp[i] = 0;
}
__global__ void hist_k(const int* __restrict__ ew) {
    int i = blockIdx.x * blockDim.x + threadIdx.x;
    if (i >= ETOT) return;
    int d = (i < EG) ? edge_at(ew, (long long)EG + i) : (i - EG);
    atomicAdd(&g_wp[d], 1);
}
__global__ void part_k() {
    __shared__ int sm[256];
    int i = blockIdx.x * 256 + threadIdx.x;
    int v = (i < NN) ? g_wp[i] : 0;
    sm[threadIdx.x] = v;
    __syncthreads();
    for (int off = 128; off; off >>= 1) {
        if (threadIdx.x < off) sm[threadIdx.x] += sm[threadIdx.x + off];
        __syncthreads();
    }
    if (threadIdx.x == 0) g_bsum[blockIdx.x] = sm[0];
}
__global__ void bscan_k() {
    __shared__ int sm[512];
    int t = threadIdx.x;
    int v = (t < SCB) ? g_bsum[t] : 0;
    sm[t] = v;
    __syncthreads();
    for (int off = 1; off < 512; off <<= 1) {
        int u = (t >= off) ? sm[t - off] : 0;
        __syncthreads();
        sm[t] += u;
        __syncthreads();
    }
    if (t < SCB) g_bsum[t] = sm[t] - v;
}
__global__ void final_k() {
    __shared__ int sm[256];
    int b = blockIdx.x, t = threadIdx.x;
    int i = b * 256 + t;
    int v = (i < NN) ? g_wp[i] : 0;
    sm[t] = v;
    __syncthreads();
    for (int off = 1; off < 256; off <<= 1) {
        int u = (t >= off) ? sm[t - off] : 0;
        __syncthreads();
        sm[t] += u;
        __syncthreads();
    }
    int exc = g_bsum[b] + sm[t] - v;
    if (i < NN) { g_rowptr[i] = exc; g_wp[i] = exc; }
    if (i == NN - 1) g_rowptr[NN] = g_bsum[b] + sm[t];
}
__global__ void scatter_k(const int* __restrict__ ew) {
    int i = blockIdx.x * blockDim.x + threadIdx.x;
    if (i >= ETOT) return;
    int s, d;
    if (i < EG) { s = edge_at(ew, i); d = edge_at(ew, (long long)EG + i); }
    else { s = d = i - EG; }
    int pos = atomicAdd(&g_wp[d], 1);
    g_col[pos] = s;
}

// ---------------- split / transpose prep ----------------
__global__ void prepw_k(const float* __restrict__ W, int which, int K, int Nc) {
    int i = blockIdx.x * 256 + threadIdx.x;
    if (i >= K * Nc) return;
    int k = i / Nc, n = i % Nc;
    float v = W[i];
    __half h = __float2half(v);
    __half l = __float2half(v - __half2float(h));
    size_t o = (size_t)n * K + k;
    if (which == 0)      { g_w0t_hi[o] = h; g_w0t_lo[o] = l; }
    else if (which == 1) { g_w1t_hi[o] = h; g_w1t_lo[o] = l; }
    else                 { g_w2t_hi[o] = h; g_w2t_lo[o] = l; }
}
// vectorized fp16 convert: float4 in, 4 halves out per thread
__global__ void prepx_k(const float* __restrict__ x) {
    int i = blockIdx.x * 256 + threadIdx.x;       // quad index
    if (i >= (NN * NFEAT) / 4) return;
    float4 v = ((const float4*)x)[i];
    __half2 p01 = __floats2half2_rn(v.x, v.y);
    __half2 p23 = __floats2half2_rn(v.z, v.w);
    uint2 hp; hp.x = *(uint32_t*)&p01; hp.y = *(uint32_t*)&p23;
    ((uint2*)g_xa)[i] = hp;
}

// ---------------- fp16 HMMA GEMM: C[M,Nc] = A[M,K] @ Wt[Nc,K]^T ----------------
// Numerics: A single fp16; B = bh + bl fp16 split. D = a*bh + a*bl (2 MMAs).
// CTA tile 128x128, 16 warps (4m x 4n), warp tile 32x32, K-chunk 64.
// 2-stage cp.async pipeline; smem XOR-swizzled. Fused al_s/al_d epilogue.
// h written to g_h as fp16 (halves agg gather traffic).
#define STAGE_BYTES 49152      // 3 tiles x 16KB
#define SM_A    0
#define SM_B_HI 16384
#define SM_B_LO 32768
#define SM_ALS  (2 * STAGE_BYTES)
#define SM_ALD  (2 * STAGE_BYTES + 1024)
#define SMEM_MM (2 * STAGE_BYTES + 2048)

template <int LAYER>
__global__ void __launch_bounds__(512) mm_k(const float* __restrict__ asrc,
                                            const float* __restrict__ adst)
{
    constexpr int K  = (LAYER == 0) ? NFEAT : HID;
    constexpr int Nc = (LAYER == 2) ? NOUTF : HID;
    constexpr int NCH = K / 64;

    extern __shared__ char smem[];
    uint32_t sb = smem_u32(smem);
    float* sals = (float*)(smem + SM_ALS);
    float* sald = (float*)(smem + SM_ALD);

    int tid = threadIdx.x, w = tid >> 5, lane = tid & 31;
    int wm = w >> 2, wn = w & 3;          // 4m x 4n warp grid, warp tile 32x32
    int row0 = blockIdx.y * 128, colblk = blockIdx.x * 128;

    const __half* A   = (LAYER == 0) ? g_xa : g_fa;
    const __half* Bhi = (LAYER == 0) ? g_w0t_hi : (LAYER == 1) ? g_w1t_hi : g_w2t_hi;
    const __half* Blo = (LAYER == 0) ? g_w0t_lo : (LAYER == 1) ? g_w1t_lo : g_w2t_lo;

    if (tid < 256) { sals[tid] = 0.f; sald[tid] = 0.f; }

    // per-thread fill coordinates (2 x 16B per tile per thread; 1024 chunks/tile)
    int fr[2], fc[2];
    uint32_t fsw[2];
#pragma unroll
    for (int l = 0; l < 2; l++) {
        int f = tid + 512 * l;
        fr[l] = f >> 3; fc[l] = f & 7;
        fsw[l] = (uint32_t)fr[l] * 128 + (((uint32_t)(fc[l] ^ (fr[l] & 7))) << 4);
    }

    auto prefetch = [&](int ch, int stage) {
        uint32_t stb = sb + stage * STAGE_BYTES;
        int kk = ch * 64;
#pragma unroll
        for (int l = 0; l < 2; l++) {
            int r = fr[l], c = fc[l];
            int gr = row0 + r;
            uint32_t asz = (gr < NN) ? 16u : 0u;
            int gra = (gr < NN) ? gr : 0;
            cpasync16(stb + SM_A + fsw[l], A + (size_t)gra * K + kk + c * 8, asz);
            cpasync16(stb + SM_B_HI + fsw[l], Bhi + (size_t)(colblk + r) * K + kk + c * 8, 16u);
            cpasync16(stb + SM_B_LO + fsw[l], Blo + (size_t)(colblk + r) * K + kk + c * 8, 16u);
        }
        CP_COMMIT();
    };

    float acc[2][4][4];
#pragma unroll
    for (int mf = 0; mf < 2; mf++)
#pragma unroll
        for (int nf = 0; nf < 4; nf++)
#pragma unroll
            for (int j = 0; j < 4; j++) acc[mf][nf][j] = 0.f;

    prefetch(0, 0);

    for (int ch = 0; ch < NCH; ch++) {
        int stage = ch & 1;
        if (ch + 1 < NCH) {
            prefetch(ch + 1, (ch + 1) & 1);
            CP_WAIT(1);            // stage `ch` complete; ch+1 still in flight
        } else {
            CP_WAIT(0);
        }
        __syncthreads();

        uint32_t stb = sb + stage * STAGE_BYTES;
#pragma unroll
        for (int s = 0; s < 4; s++) {
            uint32_t af[2][4], bh[4][2], bl[4][2];
            // A fragments (x4): lanes 0-7 m0, 8-15 m1(+8 rows), 16-23 m2(+16B k), 24-31 m3
            int rsel = (lane & 7) + ((lane >> 3) & 1) * 8;
            int kca = 2 * s + (lane >> 4);
#pragma unroll
            for (int mf = 0; mf < 2; mf++) {
                int row = wm * 32 + mf * 16 + rsel;
                uint32_t off = (uint32_t)row * 128 + (((uint32_t)(kca ^ (row & 7))) << 4);
                ldmx4(af[mf], stb + SM_A + off);
            }
            // B fragments: one x4 covers 2 n-tiles x 2 k-halves.
            int g = lane >> 3;                      // 0..3
            int brow_sub = ((g >> 1) << 3) + (lane & 7);
            int kcb = 2 * s + (g & 1);
#pragma unroll
            for (int nfp = 0; nfp < 2; nfp++) {
                int nrow = wn * 32 + nfp * 16 + brow_sub;
                uint32_t off = (uint32_t)nrow * 128 + (((uint32_t)(kcb ^ (nrow & 7))) << 4);
                uint32_t rh[4], rl[4];
                ldmx4(rh, stb + SM_B_HI + off);
                ldmx4(rl, stb + SM_B_LO + off);
                bh[nfp * 2 + 0][0] = rh[0]; bh[nfp * 2 + 0][1] = rh[1];
                bh[nfp * 2 + 1][0] = rh[2]; bh[nfp * 2 + 1][1] = rh[3];
                bl[nfp * 2 + 0][0] = rl[0]; bl[nfp * 2 + 0][1] = rl[1];
                bl[nfp * 2 + 1][0] = rl[2]; bl[nfp * 2 + 1][1] = rl[3];
            }
#pragma unroll
            for (int mf = 0; mf < 2; mf++)
#pragma unroll
                for (int nf = 0; nf < 4; nf++) {
                    mma16816h(acc[mf][nf], af[mf], bh[nf]);
                    mma16816h(acc[mf][nf], af[mf], bl[nf]);
                }
        }
        __syncthreads();   // all reads of this stage done before it's refilled
    }

    // epilogue: write C (fp16) + fused al_s/al_d row dots (fp32)
    int hl = wn >> 1;      // head-local: cols [0,64) -> 0, [64,128) -> 1
#pragma unroll
    for (int mf = 0; mf < 2; mf++) {
        int lr0 = wm * 32 + mf * 16 + (lane >> 2);
        int row_a = row0 + lr0;
        int row_b = row_a + 8;
        float ps0 = 0.f, pd0 = 0.f, ps8 = 0.f, pd8 = 0.f;
#pragma unroll
        for (int nf = 0; nf < 4; nf++) {
            float* c = acc[mf][nf];
            int colg = colblk + wn * 32 + nf * 8 + (lane & 3) * 2;
            if (row_a < NN) {
                __half2 p = __floats2half2_rn(c[0], c[1]);
                *(uint32_t*)(g_h + (size_t)row_a * Nc + colg) = *(uint32_t*)&p;
            }
            if (row_b < NN) {
                __half2 p = __floats2half2_rn(c[2], c[3]);
                *(uint32_t*)(g_h + (size_t)row_b * Nc + colg) = *(uint32_t*)&p;
            }
            float w0s = asrc[colg], w1s = asrc[colg + 1];
            float w0d = adst[colg], w1d = adst[colg + 1];
            ps0 += c[0] * w0s + c[1] * w1s; pd0 += c[0] * w0d + c[1] * w1d;
            ps8 += c[2] * w0s + c[3] * w1s; pd8 += c[2] * w0d + c[3] * w1d;
        }
#pragma unroll
        for (int off = 1; off <= 2; off <<= 1) {
            ps0 += __shfl_xor_sync(0xffffffffu, ps0, off);
            pd0 += __shfl_xor_sync(0xffffffffu, pd0, off);
            ps8 += __shfl_xor_sync(0xffffffffu, ps8, off);
            pd8 += __shfl_xor_sync(0xffffffffu, pd8, off);
        }
        if ((lane & 3) == 0) {
            atomicAdd(&sals[lr0 * 2 + hl], ps0);
            atomicAdd(&sald[lr0 * 2 + hl], pd0);
            atomicAdd(&sals[(lr0 + 8) * 2 + hl], ps8);
            atomicAdd(&sald[(lr0 + 8) * 2 + hl], pd8);
        }
    }
    __syncthreads();

    if (LAYER == 2) {
        if (tid < 128) {
            int row = row0 + tid;
            if (row < NN) {
                g_als[row] = sals[tid * 2] + sals[tid * 2 + 1];
                g_ald[row] = sald[tid * 2] + sald[tid * 2 + 1];
            }
        }
    } else {
        if (tid < 256) {
            int lr = tid >> 1, h = tid & 1;
            int row = row0 + lr;
            int head = blockIdx.x * 2 + h;
            if (row < NN) {
                g_als[row * 4 + head] = sals[tid];
                g_ald[row * 4 + head] = sald[tid];
            }
        }
    }
}

// ---------------- fused softmax + aggregation + bias (+ELU), warp per dst node ----------------
// h gathered as fp16 (uint4/uint2 per lane), accumulated in fp32.
template <int H, int C, bool ELU, int OUT_MODE>   // OUT_MODE 0: fp16 feat; 1: fp32 out
__global__ void __launch_bounds__(256) agg_k(
    const float* __restrict__ bias, float* __restrict__ outp)
{
    constexpr int HC = H * C;
    constexpr int CPL = HC / 32;   // channels per lane: 8 (layers 0/1) or 4 (layer 2)
    int nd = (blockIdx.x * blockDim.x + threadIdx.x) >> 5;
    int lane = threadIdx.x & 31;
    if (nd >= NN) return;
    int beg = g_rowptr[nd], end = g_rowptr[nd + 1];

    int ch0 = lane * CPL;
    int head = ch0 / C;            // all CPL channels of a lane share one head

    float aldv = (lane < H) ? g_ald[nd * H + lane] : 0.f;

    float acc[CPL];
#pragma unroll
    for (int j = 0; j < CPL; j++) acc[j] = 0.f;
    float denom = 0.f;

    for (int e = beg; e < end; e++) {
        int s = g_col[e];
        float exh = 0.f;
        if (lane < H) {
            float ev = g_als[s * H + lane] + aldv;
            ev = ev > 0.f ? ev : 0.2f * ev;
            exh = __expf(ev);
            denom += exh;
        }
        const __half* hv = g_h + (size_t)s * HC + ch0;
        float a = __shfl_sync(0xffffffffu, exh, head);
        if (CPL == 8) {
            uint4 pk = *(const uint4*)hv;
            const __half2* hp = (const __half2*)&pk;
#pragma unroll
            for (int j = 0; j < 4; j++) {
                float2 f = __half22float2(hp[j]);
                acc[2 * j + 0] += a * f.x;
                acc[2 * j + 1] += a * f.y;
            }
        } else {
            uint2 pk = *(const uint2*)hv;
            const __half2* hp = (const __half2*)&pk;
#pragma unroll
            for (int j = 0; j < 2; j++) {
                float2 f = __half22float2(hp[j]);
                acc[2 * j + 0] += a * f.x;
                acc[2 * j + 1] += a * f.y;
            }
        }
    }

    float den = __shfl_sync(0xffffffffu, denom, head) + 1e-16f;
    float inv = 1.f / den;
    float o[CPL];
#pragma unroll
    for (int j = 0; j < CPL; j++) {
        o[j] = acc[j] * inv + bias[ch0 + j];
        if (ELU) o[j] = o[j] > 0.f ? o[j] : expm1f(o[j]);
    }

    if (OUT_MODE == 1) {
        float* op = outp + (size_t)nd * HC + ch0;
#pragma unroll
        for (int j = 0; j < CPL; j += 4)
            *(float4*)(op + j) = make_float4(o[j], o[j + 1], o[j + 2], o[j + 3]);
    } else {
        __half* fp = g_fa + (size_t)nd * HC + ch0;
        uint32_t pk[CPL / 2];
#pragma unroll
        for (int j = 0; j < CPL / 2; j++) {
            __half2 p = __floats2half2_rn(o[2 * j], o[2 * j + 1]);
            pk[j] = *(uint32_t*)&p;
        }
        if (CPL == 8) *(uint4*)fp = *(uint4*)pk;
        else          *(uint2*)fp = *(uint2*)pk;
    }
}

// ---------------- launch ----------------
extern "C" void kernel_launch(void* const* d_in, const int* in_sizes, int n_in,
                              void* d_out, int out_size)
{
    const float* x   = (const float*)d_in[0];
    const int*   ew  = (const int*)d_in[1];
    const float* W0  = (const float*)d_in[2];
    const float* as0 = (const float*)d_in[3];
    const float* ad0 = (const float*)d_in[4];
    const float* b0  = (const float*)d_in[5];
    const float* W1  = (const float*)d_in[6];
    const float* as1 = (const float*)d_in[7];
    const float* ad1 = (const float*)d_in[8];
    const float* b1  = (const float*)d_in[9];
    const float* W2  = (const float*)d_in[10];
    const float* as2 = (const float*)d_in[11];
    const float* ad2 = (const float*)d_in[12];
    const float* b2  = (const float*)d_in[13];
    float* out = (float*)d_out;

    cudaFuncSetAttribute(mm_k<0>, cudaFuncAttributeMaxDynamicSharedMemorySize, SMEM_MM);
    cudaFuncSetAttribute(mm_k<1>, cudaFuncAttributeMaxDynamicSharedMemorySize, SMEM_MM);
    cudaFuncSetAttribute(mm_k<2>, cudaFuncAttributeMaxDynamicSharedMemorySize, SMEM_MM);

    int warp_blocks = (NN * 32 + 255) / 256;
    int mtiles = (NN + 127) / 128;

    // launches 1-3: prep needed by mm_k<0>; launch 4 = mm_k<0> (ncu captures launch #4)
    prepw_k<<<(NFEAT * HID + 255) / 256, 256>>>(W0, 0, NFEAT, HID);
    prepx_k<<<((NN * NFEAT / 4) + 255) / 256, 256>>>(x);
    prepw_k<<<(HID * HID + 255) / 256, 256>>>(W1, 1, HID, HID);
    mm_k<0><<<dim3(2, mtiles), 512, SMEM_MM>>>(as0, ad0);

    // remaining prep + CSR build
    prepw_k<<<(HID * NOUTF + 255) / 256, 256>>>(W2, 2, HID, NOUTF);
    detect_k<<<1, 1>>>(ew);
    zero_wp<<<(NN + 256) / 256, 256>>>();
    hist_k<<<(ETOT + 255) / 256, 256>>>(ew);
    part_k<<<SCB, 256>>>();
    bscan_k<<<1, 512>>>();
    final_k<<<SCB, 256>>>();
    scatter_k<<<(ETOT + 255) / 256, 256>>>(ew);

    // layer 0 aggregation
    agg_k<4, 64, true, 0><<<warp_blocks, 256>>>(b0, nullptr);
    // layer 1
    mm_k<1><<<dim3(2, mtiles), 512, SMEM_MM>>>(as1, ad1);
    agg_k<4, 64, true, 0><<<warp_blocks, 256>>>(b1, nullptr);
    // layer 2
    mm_k<2><<<dim3(1, mtiles), 512, SMEM_MM>>>(as2, ad2);
    agg_k<1, 128, false, 1><<<warp_blocks, 256>>>(b2, out);
}

// round 17
// speedup vs baseline: 1.3009x; 1.1449x over previous
#include <cuda_runtime.h>
#include <cuda_fp16.h>
#include <math.h>
#include <cstdint>

#define NN 100000
#define EG 400000
#define NFEAT 128
#define HID 256
#define NOUTF 128
#define ETOT (EG + NN)
#define SCB ((NN + 255) / 256)

// ---------------- scratch (device globals; no allocation allowed) ----------------
__device__ __half g_h[(size_t)NN * HID];           // transformed features h (fp16)
__device__ __half g_xa[(size_t)NN * NFEAT];        // input features, fp16
__device__ __half g_fa[(size_t)NN * HID];          // layer activations, fp16
__device__ __half g_w0t[HID * NFEAT];              // [N][K] fp16 weights (transposed)
__device__ __half g_w1t[HID * HID];
__device__ __half g_w2t[NOUTF * HID];
__device__ float g_als[NN * 4];
__device__ float g_ald[NN * 4];
__device__ int   g_rowptr[NN + 1];
__device__ int   g_wp[NN + 1];
__device__ int   g_bsum[SCB + 1];
__device__ int   g_col[ETOT];
__device__ int   g_is64;

// ---------------- warp-MMA helpers (portable PTX, sm_80+) ----------------
__device__ __forceinline__ uint32_t smem_u32(const void* p) {
    uint32_t a;
    asm("{ .reg .u64 t; cvta.to.shared.u64 t, %1; cvt.u32.u64 %0, t; }" : "=r"(a) : "l"(p));
    return a;
}
__device__ __forceinline__ void ldmx4(uint32_t* r, uint32_t addr) {
    asm volatile("ldmatrix.sync.aligned.m8n8.x4.shared.b16 {%0,%1,%2,%3}, [%4];"
                 : "=r"(r[0]), "=r"(r[1]), "=r"(r[2]), "=r"(r[3]) : "r"(addr));
}
__device__ __forceinline__ void mma16816h(float* c, const uint32_t* a, const uint32_t* b) {
    asm volatile("mma.sync.aligned.m16n8k16.row.col.f32.f16.f16.f32 "
                 "{%0,%1,%2,%3}, {%4,%5,%6,%7}, {%8,%9}, {%0,%1,%2,%3};"
                 : "+f"(c[0]), "+f"(c[1]), "+f"(c[2]), "+f"(c[3])
                 : "r"(a[0]), "r"(a[1]), "r"(a[2]), "r"(a[3]), "r"(b[0]), "r"(b[1]));
}
__device__ __forceinline__ void cpasync16(uint32_t saddr, const void* gptr, uint32_t srcsz) {
    asm volatile("cp.async.cg.shared.global [%0], [%1], 16, %2;"
                 :: "r"(saddr), "l"(gptr), "r"(srcsz) : "memory");
}
#define CP_COMMIT() asm volatile("cp.async.commit_group;" ::: "memory")
#define CP_WAIT(n)  asm volatile("cp.async.wait_group %0;" :: "n"(n) : "memory")

// ---------------- edge dtype sniffer ----------------
__global__ void detect_k(const int* __restrict__ ew) {
    int all_zero = 1;
    for (int i = 0; i < 64; i++)
        if (ew[2 * i + 1] != 0) { all_zero = 0; break; }
    g_is64 = all_zero;
}
__device__ __forceinline__ int edge_at(const int* ew, long long idx) {
    return g_is64 ? ew[2 * idx] : ew[idx];
}

// ---------------- CSR build ----------------
__global__ void zero_wp() {
    int i = blockIdx.x * blockDim.x + threadIdx.x;
    if (i <= NN) g_wp[i] = 0;
}
__global__ void hist_k(const int* __restrict__ ew) {
    int i = blockIdx.x * blockDim.x + threadIdx.x;
    if (i >= ETOT) return;
    int d = (i < EG) ? edge_at(ew, (long long)EG + i) : (i - EG);
    atomicAdd(&g_wp[d], 1);
}
__global__ void part_k() {
    __shared__ int sm[256];
    int i = blockIdx.x * 256 + threadIdx.x;
    int v = (i < NN) ? g_wp[i] : 0;
    sm[threadIdx.x] = v;
    __syncthreads();
    for (int off = 128; off; off >>= 1) {
        if (threadIdx.x < off) sm[threadIdx.x] += sm[threadIdx.x + off];
        __syncthreads();
    }
    if (threadIdx.x == 0) g_bsum[blockIdx.x] = sm[0];
}
__global__ void bscan_k() {
    __shared__ int sm[512];
    int t = threadIdx.x;
    int v = (t < SCB) ? g_bsum[t] : 0;
    sm[t] = v;
    __syncthreads();
    for (int off = 1; off < 512; off <<= 1) {
        int u = (t >= off) ? sm[t - off] : 0;
        __syncthreads();
        sm[t] += u;
        __syncthreads();
    }
    if (t < SCB) g_bsum[t] = sm[t] - v;
}
__global__ void final_k() {
    __shared__ int sm[256];
    int b = blockIdx.x, t = threadIdx.x;
    int i = b * 256 + t;
    int v = (i < NN) ? g_wp[i] : 0;
    sm[t] = v;
    __syncthreads();
    for (int off = 1; off < 256; off <<= 1) {
        int u = (t >= off) ? sm[t - off] : 0;
        __syncthreads();
        sm[t] += u;
        __syncthreads();
    }
    int exc = g_bsum[b] + sm[t] - v;
    if (i < NN) { g_rowptr[i] = exc; g_wp[i] = exc; }
    if (i == NN - 1) g_rowptr[NN] = g_bsum[b] + sm[t];
}
__global__ void scatter_k(const int* __restrict__ ew) {
    int i = blockIdx.x * blockDim.x + threadIdx.x;
    if (i >= ETOT) return;
    int s, d;
    if (i < EG) { s = edge_at(ew, i); d = edge_at(ew, (long long)EG + i); }
    else { s = d = i - EG; }
    int pos = atomicAdd(&g_wp[d], 1);
    g_col[pos] = s;
}

// ---------------- weight transpose + fp16 convert ----------------
__global__ void prepw_k(const float* __restrict__ W, int which, int K, int Nc) {
    int i = blockIdx.x * 256 + threadIdx.x;
    if (i >= K * Nc) return;
    int k = i / Nc, n = i % Nc;
    __half h = __float2half(W[i]);
    size_t o = (size_t)n * K + k;
    if (which == 0)      g_w0t[o] = h;
    else if (which == 1) g_w1t[o] = h;
    else                 g_w2t[o] = h;
}
// vectorized fp16 convert: float4 in, 4 halves out per thread
__global__ void prepx_k(const float* __restrict__ x) {
    int i = blockIdx.x * 256 + threadIdx.x;       // quad index
    if (i >= (NN * NFEAT) / 4) return;
    float4 v = ((const float4*)x)[i];
    __half2 p01 = __floats2half2_rn(v.x, v.y);
    __half2 p23 = __floats2half2_rn(v.z, v.w);
    uint2 hp; hp.x = *(uint32_t*)&p01; hp.y = *(uint32_t*)&p23;
    ((uint2*)g_xa)[i] = hp;
}

// ---------------- fp16 HMMA GEMM: C[M,Nc] = A[M,K] @ Wt[Nc,K]^T ----------------
// Pure fp16 operands, fp32 accumulate, 1 MMA per tile-step.
// CTA tile 128x128, 16 warps (4m x 4n), warp tile 32x32, K-chunk 64.
// 2-stage cp.async pipeline; smem XOR-swizzled. Fused al_s/al_d epilogue.
// h written to g_h as fp16.
#define STAGE_BYTES 32768      // 2 tiles x 16KB
#define SM_A    0
#define SM_B    16384
#define SM_ALS  (2 * STAGE_BYTES)
#define SM_ALD  (2 * STAGE_BYTES + 1024)
#define SMEM_MM (2 * STAGE_BYTES + 2048)

template <int LAYER>
__global__ void __launch_bounds__(512) mm_k(const float* __restrict__ asrc,
                                            const float* __restrict__ adst)
{
    constexpr int K  = (LAYER == 0) ? NFEAT : HID;
    constexpr int Nc = (LAYER == 2) ? NOUTF : HID;
    constexpr int NCH = K / 64;

    extern __shared__ char smem[];
    uint32_t sb = smem_u32(smem);
    float* sals = (float*)(smem + SM_ALS);
    float* sald = (float*)(smem + SM_ALD);

    int tid = threadIdx.x, w = tid >> 5, lane = tid & 31;
    int wm = w >> 2, wn = w & 3;          // 4m x 4n warp grid, warp tile 32x32
    int row0 = blockIdx.y * 128, colblk = blockIdx.x * 128;

    const __half* A  = (LAYER == 0) ? g_xa : g_fa;
    const __half* Bw = (LAYER == 0) ? g_w0t : (LAYER == 1) ? g_w1t : g_w2t;

    if (tid < 256) { sals[tid] = 0.f; sald[tid] = 0.f; }

    // per-thread fill coordinates (2 x 16B per tile per thread; 1024 chunks/tile)
    int fr[2], fc[2];
    uint32_t fsw[2];
#pragma unroll
    for (int l = 0; l < 2; l++) {
        int f = tid + 512 * l;
        fr[l] = f >> 3; fc[l] = f & 7;
        fsw[l] = (uint32_t)fr[l] * 128 + (((uint32_t)(fc[l] ^ (fr[l] & 7))) << 4);
    }

    auto prefetch = [&](int ch, int stage) {
        uint32_t stb = sb + stage * STAGE_BYTES;
        int kk = ch * 64;
#pragma unroll
        for (int l = 0; l < 2; l++) {
            int r = fr[l], c = fc[l];
            int gr = row0 + r;
            uint32_t asz = (gr < NN) ? 16u : 0u;
            int gra = (gr < NN) ? gr : 0;
            cpasync16(stb + SM_A + fsw[l], A + (size_t)gra * K + kk + c * 8, asz);
            cpasync16(stb + SM_B + fsw[l], Bw + (size_t)(colblk + r) * K + kk + c * 8, 16u);
        }
        CP_COMMIT();
    };

    float acc[2][4][4];
#pragma unroll
    for (int mf = 0; mf < 2; mf++)
#pragma unroll
        for (int nf = 0; nf < 4; nf++)
#pragma unroll
            for (int j = 0; j < 4; j++) acc[mf][nf][j] = 0.f;

    prefetch(0, 0);

    for (int ch = 0; ch < NCH; ch++) {
        int stage = ch & 1;
        if (ch + 1 < NCH) {
            prefetch(ch + 1, (ch + 1) & 1);
            CP_WAIT(1);            // stage `ch` complete; ch+1 still in flight
        } else {
            CP_WAIT(0);
        }
        __syncthreads();

        uint32_t stb = sb + stage * STAGE_BYTES;
#pragma unroll
        for (int s = 0; s < 4; s++) {
            uint32_t af[2][4], bf[4][2];
            // A fragments (x4): lanes 0-7 m0, 8-15 m1(+8 rows), 16-23 m2(+16B k), 24-31 m3
            int rsel = (lane & 7) + ((lane >> 3) & 1) * 8;
            int kca = 2 * s + (lane >> 4);
#pragma unroll
            for (int mf = 0; mf < 2; mf++) {
                int row = wm * 32 + mf * 16 + rsel;
                uint32_t off = (uint32_t)row * 128 + (((uint32_t)(kca ^ (row & 7))) << 4);
                ldmx4(af[mf], stb + SM_A + off);
            }
            // B fragments: one x4 covers 2 n-tiles x 2 k-halves.
            int g = lane >> 3;                      // 0..3
            int brow_sub = ((g >> 1) << 3) + (lane & 7);
            int kcb = 2 * s + (g & 1);
#pragma unroll
            for (int nfp = 0; nfp < 2; nfp++) {
                int nrow = wn * 32 + nfp * 16 + brow_sub;
                uint32_t off = (uint32_t)nrow * 128 + (((uint32_t)(kcb ^ (nrow & 7))) << 4);
                uint32_t rb[4];
                ldmx4(rb, stb + SM_B + off);
                bf[nfp * 2 + 0][0] = rb[0]; bf[nfp * 2 + 0][1] = rb[1];
                bf[nfp * 2 + 1][0] = rb[2]; bf[nfp * 2 + 1][1] = rb[3];
            }
#pragma unroll
            for (int mf = 0; mf < 2; mf++)
#pragma unroll
                for (int nf = 0; nf < 4; nf++)
                    mma16816h(acc[mf][nf], af[mf], bf[nf]);
        }
        __syncthreads();   // all reads of this stage done before it's refilled
    }

    // epilogue: write C (fp16) + fused al_s/al_d row dots (fp32)
    int hl = wn >> 1;      // head-local: cols [0,64) -> 0, [64,128) -> 1
#pragma unroll
    for (int mf = 0; mf < 2; mf++) {
        int lr0 = wm * 32 + mf * 16 + (lane >> 2);
        int row_a = row0 + lr0;
        int row_b = row_a + 8;
        float ps0 = 0.f, pd0 = 0.f, ps8 = 0.f, pd8 = 0.f;
#pragma unroll
        for (int nf = 0; nf < 4; nf++) {
            float* c = acc[mf][nf];
            int colg = colblk + wn * 32 + nf * 8 + (lane & 3) * 2;
            if (row_a < NN) {
                __half2 p = __floats2half2_rn(c[0], c[1]);
                *(uint32_t*)(g_h + (size_t)row_a * Nc + colg) = *(uint32_t*)&p;
            }
            if (row_b < NN) {
                __half2 p = __floats2half2_rn(c[2], c[3]);
                *(uint32_t*)(g_h + (size_t)row_b * Nc + colg) = *(uint32_t*)&p;
            }
            float w0s = asrc[colg], w1s = asrc[colg + 1];
            float w0d = adst[colg], w1d = adst[colg + 1];
            ps0 += c[0] * w0s + c[1] * w1s; pd0 += c[0] * w0d + c[1] * w1d;
            ps8 += c[2] * w0s + c[3] * w1s; pd8 += c[2] * w0d + c[3] * w1d;
        }
#pragma unroll
        for (int off = 1; off <= 2; off <<= 1) {
            ps0 += __shfl_xor_sync(0xffffffffu, ps0, off);
            pd0 += __shfl_xor_sync(0xffffffffu, pd0, off);
            ps8 += __shfl_xor_sync(0xffffffffu, ps8, off);
            pd8 += __shfl_xor_sync(0xffffffffu, pd8, off);
        }
        if ((lane & 3) == 0) {
            atomicAdd(&sals[lr0 * 2 + hl], ps0);
            atomicAdd(&sald[lr0 * 2 + hl], pd0);
            atomicAdd(&sals[(lr0 + 8) * 2 + hl], ps8);
            atomicAdd(&sald[(lr0 + 8) * 2 + hl], pd8);
        }
    }
    __syncthreads();

    if (LAYER == 2) {
        if (tid < 128) {
            int row = row0 + tid;
            if (row < NN) {
                g_als[row] = sals[tid * 2] + sals[tid * 2 + 1];
                g_ald[row] = sald[tid * 2] + sald[tid * 2 + 1];
            }
        }
    } else {
        if (tid < 256) {
            int lr = tid >> 1, h = tid & 1;
            int row = row0 + lr;
            int head = blockIdx.x * 2 + h;
            if (row < NN) {
                g_als[row * 4 + head] = sals[tid];
                g_ald[row * 4 + head] = sald[tid];
            }
        }
    }
}

// ---------------- fused softmax + aggregation + bias (+ELU), warp per dst node ----------------
// h gathered as fp16 (uint4/uint2 per lane), accumulated in fp32.
template <int H, int C, bool ELU, int OUT_MODE>   // OUT_MODE 0: fp16 feat; 1: fp32 out
__global__ void __launch_bounds__(256) agg_k(
    const float* __restrict__ bias, float* __restrict__ outp)
{
    constexpr int HC = H * C;
    constexpr int CPL = HC / 32;   // channels per lane: 8 (layers 0/1) or 4 (layer 2)
    int nd = (blockIdx.x * blockDim.x + threadIdx.x) >> 5;
    int lane = threadIdx.x & 31;
    if (nd >= NN) return;
    int beg = g_rowptr[nd], end = g_rowptr[nd + 1];

    int ch0 = lane * CPL;
    int head = ch0 / C;            // all CPL channels of a lane share one head

    float aldv = (lane < H) ? g_ald[nd * H + lane] : 0.f;

    float acc[CPL];
#pragma unroll
    for (int j = 0; j < CPL; j++) acc[j] = 0.f;
    float denom = 0.f;

    for (int e = beg; e < end; e++) {
        int s = g_col[e];
        float exh = 0.f;
        if (lane < H) {
            float ev = g_als[s * H + lane] + aldv;
            ev = ev > 0.f ? ev : 0.2f * ev;
            exh = __expf(ev);
            denom += exh;
        }
        const __half* hv = g_h + (size_t)s * HC + ch0;
        float a = __shfl_sync(0xffffffffu, exh, head);
        if (CPL == 8) {
            uint4 pk = *(const uint4*)hv;
            const __half2* hp = (const __half2*)&pk;
#pragma unroll
            for (int j = 0; j < 4; j++) {
                float2 f = __half22float2(hp[j]);
                acc[2 * j + 0] += a * f.x;
                acc[2 * j + 1] += a * f.y;
            }
        } else {
            uint2 pk = *(const uint2*)hv;
            const __half2* hp = (const __half2*)&pk;
#pragma unroll
            for (int j = 0; j < 2; j++) {
                float2 f = __half22float2(hp[j]);
                acc[2 * j + 0] += a * f.x;
                acc[2 * j + 1] += a * f.y;
            }
        }
    }

    float den = __shfl_sync(0xffffffffu, denom, head) + 1e-16f;
    float inv = 1.f / den;
    float o[CPL];
#pragma unroll
    for (int j = 0; j < CPL; j++) {
        o[j] = acc[j] * inv + bias[ch0 + j];
        if (ELU) o[j] = o[j] > 0.f ? o[j] : expm1f(o[j]);
    }

    if (OUT_MODE == 1) {
        float* op = outp + (size_t)nd * HC + ch0;
#pragma unroll
        for (int j = 0; j < CPL; j += 4)
            *(float4*)(op + j) = make_float4(o[j], o[j + 1], o[j + 2], o[j + 3]);
    } else {
        __half* fp = g_fa + (size_t)nd * HC + ch0;
        uint32_t pk[CPL / 2];
#pragma unroll
        for (int j = 0; j < CPL / 2; j++) {
            __half2 p = __floats2half2_rn(o[2 * j], o[2 * j + 1]);
            pk[j] = *(uint32_t*)&p;
        }
        if (CPL == 8) *(uint4*)fp = *(uint4*)pk;
        else          *(uint2*)fp = *(uint2*)pk;
    }
}

// ---------------- launch ----------------
extern "C" void kernel_launch(void* const* d_in, const int* in_sizes, int n_in,
                              void* d_out, int out_size)
{
    const float* x   = (const float*)d_in[0];
    const int*   ew  = (const int*)d_in[1];
    const float* W0  = (const float*)d_in[2];
    const float* as0 = (const float*)d_in[3];
    const float* ad0 = (const float*)d_in[4];
    const float* b0  = (const float*)d_in[5];
    const float* W1  = (const float*)d_in[6];
    const float* as1 = (const float*)d_in[7];
    const float* ad1 = (const float*)d_in[8];
    const float* b1  = (const float*)d_in[9];
    const float* W2  = (const float*)d_in[10];
    const float* as2 = (const float*)d_in[11];
    const float* ad2 = (const float*)d_in[12];
    const float* b2  = (const float*)d_in[13];
    float* out = (float*)d_out;

    cudaFuncSetAttribute(mm_k<0>, cudaFuncAttributeMaxDynamicSharedMemorySize, SMEM_MM);
    cudaFuncSetAttribute(mm_k<1>, cudaFuncAttributeMaxDynamicSharedMemorySize, SMEM_MM);
    cudaFuncSetAttribute(mm_k<2>, cudaFuncAttributeMaxDynamicSharedMemorySize, SMEM_MM);

    int warp_blocks = (NN * 32 + 255) / 256;
    int mtiles = (NN + 127) / 128;

    // launches 1-3: prep needed by mm_k<0>; launch 4 = mm_k<0> (ncu captures launch #4)
    prepw_k<<<(NFEAT * HID + 255) / 256, 256>>>(W0, 0, NFEAT, HID);
    prepx_k<<<((NN * NFEAT / 4) + 255) / 256, 256>>>(x);
    prepw_k<<<(HID * HID + 255) / 256, 256>>>(W1, 1, HID, HID);
    mm_k<0><<<dim3(2, mtiles), 512, SMEM_MM>>>(as0, ad0);

    // remaining prep + CSR build
    prepw_k<<<(HID * NOUTF + 255) / 256, 256>>>(W2, 2, HID, NOUTF);
    detect_k<<<1, 1>>>(ew);
    zero_wp<<<(NN + 256) / 256, 256>>>();
    hist_k<<<(ETOT + 255) / 256, 256>>>(ew);
    part_k<<<SCB, 256>>>();
    bscan_k<<<1, 512>>>();
    final_k<<<SCB, 256>>>();
    scatter_k<<<(ETOT + 255) / 256, 256>>>(ew);

    // layer 0 aggregation
    agg_k<4, 64, true, 0><<<warp_blocks, 256>>>(b0, nullptr);
    // layer 1
    mm_k<1><<<dim3(2, mtiles), 512, SMEM_MM>>>(as1, ad1);
    agg_k<4, 64, true, 0><<<warp_blocks, 256>>>(b1, nullptr);
    // layer 2
    mm_k<2><<<dim3(1, mtiles), 512, SMEM_MM>>>(as2, ad2);
    agg_k<1, 128, false, 1><<<warp_blocks, 256>>>(b2, out);
}